// round 17
// baseline (speedup 1.0000x reference)
#include <cuda_runtime.h>
#include <cuda_fp16.h>

// cumulative_hazard R15: R13 + ILP forcing.
//  - __launch_bounds__(256,1): stop ptxas register-minimizing (38 regs) and
//    serializing the 4 independent mma->tanh chains.
//  - Phase-separated RNN inner loop: all c-inits, then all 4 mmas, then all
//    8 tanhs, as adjacent independent ops.
//  - Everything else identical to R13 (LDS.128 y reads, ln2 folded, k8 d!=c).

typedef unsigned u32;

#define NTHREADS 256
#define WARPS 8
#define TILES 4
#define JPAD 12
#define ROWS_PER_BLOCK 512   // 8 warps x 64 rows

__device__ __forceinline__ __half2 u2h(u32 v) { return *reinterpret_cast<__half2*>(&v); }
__device__ __forceinline__ u32 h2u2(__half2 v) { return *reinterpret_cast<u32*>(&v); }
__device__ __forceinline__ u32 h2u(__half lo, __half hi) {
    __half2 v = __halves2half2(lo, hi);
    return *reinterpret_cast<u32*>(&v);
}
__device__ __forceinline__ u32 tanh_u(u32 v) {
    asm("tanh.approx.f16x2 %0, %0;" : "+r"(v));
    return v;
}
// mma m16n8k8 f16, separate D and C
__device__ __forceinline__ void mma1688_dc(u32& d0, u32& d1,
                                           u32 a0, u32 a1, u32 b0,
                                           u32 c0, u32 c1) {
    asm("mma.sync.aligned.m16n8k8.row.col.f16.f16.f16.f16 "
        "{%0,%1}, {%2,%3}, {%4}, {%5,%6};"
        : "=r"(d0), "=r"(d1)
        : "r"(a0), "r"(a1), "r"(b0), "r"(c0), "r"(c1));
}

__device__ __forceinline__ float softplus_out(float x) {
    float ax = fabsf(x);
    float l = log1pf(__expf(-ax));
    return x > 0.0f ? x + l : l;
}
__device__ __forceinline__ float sp_precise(float x) {
    float ax = fabsf(x);
    float l = log1pf(expf(-ax));
    return x > 0.0f ? x + l : l;
}

__global__ __launch_bounds__(NTHREADS, 1)
void hazard_kernel(const float* __restrict__ Y,     // [N,16]
                   const float* __restrict__ tau,   // [N,1]
                   const float* __restrict__ f1W,   // [8,9]
                   const float* __restrict__ f1b,   // [8]
                   const float* __restrict__ ftW,   // [8,1]
                   const float* __restrict__ ftb,   // [8]
                   const float* __restrict__ f20W,  // [8,8]
                   const float* __restrict__ f20b,  // [8]
                   const float* __restrict__ f21W,  // [8,8]
                   const float* __restrict__ f21b,  // [8]
                   const float* __restrict__ f22W,  // [1,8]
                   const float* __restrict__ f22b,  // [1]
                   float* __restrict__ out,         // [N]
                   int N)
{
    __shared__ __half sW1[72], sB1[8];
    __shared__ __half sW20[64], sB20[8], sTW[8];
    __shared__ __half sW21[64], sB21[8];
    __shared__ float  sW22f[8];
    __shared__ float  sB22f;
    // y: [warp][tile][g][j(12)] as half2(row g, row g+8); 48B row pitch, 16B aligned
    __shared__ __align__(16) u32 sY[WARPS * TILES * 8 * JPAD];
    __shared__ u32 sTau[WARPS * TILES * 8];

    const int t = threadIdx.x;
    // ---- weight preprocessing (softplus folded; f16; ln2 folded into W1 col 8) ----
    if (t < 72)        { float s = (t % 9 == 8) ? 0.69314718056f : 1.0f;
                         sW1[t] = __float2half(f1W[t] * s); }
    else if (t < 80)   { int i = t - 72;  sB1[i]  = __float2half(f1b[i]); }
    else if (t < 144)  { int i = t - 80;  sW20[i] = __float2half(f20W[i]); }
    else if (t < 152)  { int i = t - 144; sB20[i] = __float2half(f20b[i] + sp_precise(ftb[i])); }
    else if (t < 160)  { int i = t - 152; sTW[i]  = __float2half(sp_precise(ftW[i])); }
    else if (t < 224)  { int i = t - 160; sW21[i] = __float2half(sp_precise(f21W[i])); }
    else if (t < 232)  { int i = t - 224; sB21[i] = __float2half(sp_precise(f21b[i])); }
    else if (t < 240)  { int i = t - 232; sW22f[i] = sp_precise(f22W[i]); }
    else if (t == 240) { sB22f = sp_precise(f22b[0]); }
    __syncthreads();

    const int lane = t & 31;
    const int warp = t >> 5;
    const int g  = lane >> 2;   // 0..7
    const int tq = lane & 3;    // 0..3

    const long long base = (long long)blockIdx.x * ROWS_PER_BLOCK;

    // ---- stage y (log2-gaps) & tau. thread stages local rows 2t, 2t+1
    // (writer warp == owner warp). ----
    {
        const int rp = 2 * t;
        long long r0 = base + rp;
        if (r0 > (long long)N - 2) r0 = (long long)N - 2;

        const float4* yp = (const float4*)(Y + r0 * 16);
        float4 q0 = yp[0], q1 = yp[1], q2 = yp[2], q3 = yp[3];
        float4 p0 = yp[4], p1 = yp[5], p2 = yp[6], p3 = yp[7];
        float ra[16] = { q0.x,q0.y,q0.z,q0.w, q1.x,q1.y,q1.z,q1.w,
                         q2.x,q2.y,q2.z,q2.w, q3.x,q3.y,q3.z,q3.w };
        float rb[16] = { p0.x,p0.y,p0.z,p0.w, p1.x,p1.y,p1.z,p1.w,
                         p2.x,p2.y,p2.z,p2.w, p3.x,p3.y,p3.z,p3.w };

        __half* yh = reinterpret_cast<__half*>(sY);
        __half* th = reinterpret_cast<__half*>(sTau);

        const int tile = (rp >> 4) & 3;
        const int hs   = (rp >> 3) & 1;
        const int g0   = rp & 7;          // even
#pragma unroll
        for (int j = 0; j < 11; j++) {
            float d0 = __log2f(ra[4 + j] - ra[3 + j] + 0.1f);   // ln2 folded into W1 col8
            float d1 = __log2f(rb[4 + j] - rb[3 + j] + 0.1f);
            int i0 = (((warp * TILES + tile) * 8 + g0)     * JPAD + j) * 2 + hs;
            int i1 = (((warp * TILES + tile) * 8 + g0 + 1) * JPAD + j) * 2 + hs;
            yh[i0] = __float2half(d0);
            yh[i1] = __float2half(d1);
        }
        float2 tv = *(const float2*)(tau + r0);
        th[((warp * TILES + tile) * 8 + g0)     * 2 + hs] = __float2half(tv.x);
        th[((warp * TILES + tile) * 8 + g0 + 1) * 2 + hs] = __float2half(tv.y);
    }
    __syncwarp();

    // ---- per-thread fragment weights ----
    const u32 w1b0 = h2u(sW1[g * 9 + 2 * tq], sW1[g * 9 + 2 * tq + 1]);   // B: W1[n=g][k=2tq..]
    const __half2 w8p = __halves2half2(sW1[(2 * tq) * 9 + 8],             // (ln2-scaled) y weights
                                       sW1[(2 * tq + 1) * 9 + 8]);
    const __half2 bc1 = __halves2half2(sB1[2 * tq], sB1[2 * tq + 1]);
    const u32 w20b  = h2u(sW20[g * 8 + 2 * tq], sW20[g * 8 + 2 * tq + 1]);
    const __half2 b20p = __halves2half2(sB20[2 * tq], sB20[2 * tq + 1]);
    const __half2 tWp  = __halves2half2(sTW[2 * tq], sTW[2 * tq + 1]);
    const u32 w21b  = h2u(sW21[g * 8 + 2 * tq], sW21[g * 8 + 2 * tq + 1]);
    const u32 b21p  = h2u(sB21[2 * tq], sB21[2 * tq + 1]);
    const float w22a = sW22f[2 * tq], w22c = sW22f[2 * tq + 1];
    const float b22  = sB22f;

    const u32* yW  = sY + (warp * TILES) * 8 * JPAD;
    const u32* tW2 = sTau + (warp * TILES) * 8;

    // ---- RNN: 4 independent fragment chains, phase-separated for ILP ----
    u32 f0[TILES], f1r[TILES];

#pragma unroll
    for (int jg = 0; jg < 3; jg++) {
        u32 yv[TILES][4];
#pragma unroll
        for (int tile = 0; tile < TILES; tile++) {
            uint4 v = *(const uint4*)&yW[(tile * 8 + g) * JPAD + jg * 4];
            yv[tile][0] = v.x; yv[tile][1] = v.y; yv[tile][2] = v.z; yv[tile][3] = v.w;
        }
#pragma unroll
        for (int jj = 0; jj < 4; jj++) {
            const int j = jg * 4 + jj;
            if (j == 0) {
                // step 0: flow == 0 -> f = tanh(splat(y)*w8 + b)
#pragma unroll
                for (int tile = 0; tile < TILES; tile++) {
                    __half2 yh2 = u2h(yv[tile][jj]);
                    f0[tile]  = tanh_u(h2u2(__hfma2(__low2half2(yh2),  w8p, bc1)));
                    f1r[tile] = tanh_u(h2u2(__hfma2(__high2half2(yh2), w8p, bc1)));
                }
            } else if (j < 11) {
                // phase 1: all c-inits (independent of mma chain)
                u32 c[2 * TILES];
#pragma unroll
                for (int tile = 0; tile < TILES; tile++) {
                    __half2 yh2 = u2h(yv[tile][jj]);
                    c[2 * tile]     = h2u2(__hfma2(__low2half2(yh2),  w8p, bc1));
                    c[2 * tile + 1] = h2u2(__hfma2(__high2half2(yh2), w8p, bc1));
                }
                // phase 2: all 4 mmas (independent of each other)
                u32 d[2 * TILES];
#pragma unroll
                for (int tile = 0; tile < TILES; tile++) {
                    mma1688_dc(d[2 * tile], d[2 * tile + 1],
                               f0[tile], f1r[tile], w1b0,
                               c[2 * tile], c[2 * tile + 1]);
                }
                // phase 3: all 8 tanhs
#pragma unroll
                for (int tile = 0; tile < TILES; tile++) {
                    f0[tile]  = tanh_u(d[2 * tile]);
                    f1r[tile] = tanh_u(d[2 * tile + 1]);
                }
            }
        }
    }

    // ---- f2 layer 0: tanh(flow @ W20^T + b20' + tau*sp(Wtau)) ----
    {
        u32 c[2 * TILES], d[2 * TILES];
#pragma unroll
        for (int tile = 0; tile < TILES; tile++) {
            __half2 tp = u2h(tW2[tile * 8 + g]);
            c[2 * tile]     = h2u2(__hfma2(__low2half2(tp),  tWp, b20p));
            c[2 * tile + 1] = h2u2(__hfma2(__high2half2(tp), tWp, b20p));
        }
#pragma unroll
        for (int tile = 0; tile < TILES; tile++)
            mma1688_dc(d[2 * tile], d[2 * tile + 1],
                       f0[tile], f1r[tile], w20b, c[2 * tile], c[2 * tile + 1]);
#pragma unroll
        for (int tile = 0; tile < TILES; tile++) {
            f0[tile]  = tanh_u(d[2 * tile]);
            f1r[tile] = tanh_u(d[2 * tile + 1]);
        }
    }

    // ---- f2 layer 1: tanh(g @ sp(W21)^T + sp(b21)) ----
    {
        u32 d[2 * TILES];
#pragma unroll
        for (int tile = 0; tile < TILES; tile++)
            mma1688_dc(d[2 * tile], d[2 * tile + 1],
                       f0[tile], f1r[tile], w21b, b21p, b21p);
#pragma unroll
        for (int tile = 0; tile < TILES; tile++) {
            f0[tile]  = tanh_u(d[2 * tile]);
            f1r[tile] = tanh_u(d[2 * tile + 1]);
        }
    }

    // ---- output layer: f32 dot (quad-distributed) + shfl reduce ----
#pragma unroll
    for (int tile = 0; tile < TILES; tile++) {
        float2 fa = __half22float2(u2h(f0[tile]));   // row g:   cols 2tq,2tq+1
        float2 fb = __half22float2(u2h(f1r[tile]));  // row g+8
        float pl = fa.x * w22a + fa.y * w22c;
        float ph = fb.x * w22a + fb.y * w22c;
        pl += __shfl_xor_sync(0xFFFFFFFFu, pl, 1);
        pl += __shfl_xor_sync(0xFFFFFFFFu, pl, 2);
        ph += __shfl_xor_sync(0xFFFFFFFFu, ph, 1);
        ph += __shfl_xor_sync(0xFFFFFFFFu, ph, 2);
        if (tq == 0) {
            long long rlo = base + warp * 64 + tile * 16 + g;
            long long rhi = rlo + 8;
            if (rlo < N) out[rlo] = softplus_out(pl + b22);
            if (rhi < N) out[rhi] = softplus_out(ph + b22);
        }
    }
}

extern "C" void kernel_launch(void* const* d_in, const int* in_sizes, int n_in,
                              void* d_out, int out_size)
{
    const float* Y    = (const float*)d_in[0];
    const float* tau  = (const float*)d_in[1];
    const float* f1W  = (const float*)d_in[2];
    const float* f1b  = (const float*)d_in[3];
    const float* ftW  = (const float*)d_in[4];
    const float* ftb  = (const float*)d_in[5];
    const float* f20W = (const float*)d_in[6];
    const float* f20b = (const float*)d_in[7];
    const float* f21W = (const float*)d_in[8];
    const float* f21b = (const float*)d_in[9];
    const float* f22W = (const float*)d_in[10];
    const float* f22b = (const float*)d_in[11];
    float* out = (float*)d_out;

    int N = out_size;
    int blocks = (N + ROWS_PER_BLOCK - 1) / ROWS_PER_BLOCK;
    hazard_kernel<<<blocks, NTHREADS>>>(Y, tau, f1W, f1b, ftW, ftb,
                                        f20W, f20b, f21W, f21b, f22W, f22b,
                                        out, N);
}